// round 15
// baseline (speedup 1.0000x reference)
#include <cuda_runtime.h>
#include <cuda.h>
#include <cuda_bf16.h>
#include <cuda_fp8.h>
#include <cstdint>

#define NROWS 8192
#define DIM   768
#define CHUNKS 2                        // grid.y column halves
#define COLS_PER_CTA (NROWS / CHUNKS)   // 4096
#define NTILE (COLS_PER_CTA / 128)      // 32 column tiles of N=128
#define KCPT  6                         // K=128 chunks per tile (768/128)
#define NCHUNK (NTILE * KCPT)           // 192 pipeline chunks per CTA
#define NSTAGE 8                        // B pipeline depth
#define STAGE_BYTES 16384               // 128 j-rows x 128 K fp8
#define NDBUF 4                         // D buffers in TMEM
#define NTHREADS 320                    // 8 consumer + issuer + producer warps

#define EXPC  28.853900817779268f
#define EXPC2 (EXPC / 1024.0f)          // logits are 1024*sim (xn scaled by 32)
#define TSCALE (20.0f / 1024.0f)
#define LN2   0.6931471805599453f

// smem: [0] tmem ptr | [16..80) BFULL[8] | [80..144) BFREE[8]
//       [144..176) MDONE[4] | [176..208) DFREE[4] | [208..216) ABAR
//       [1024) A 6x16KB | [99328) B stages 8x16KB
#define A_OFF 1024
#define B_OFF (1024 + 6 * 16384)                      // 99328
#define SMEM_TOTAL (B_OFF + NSTAGE * STAGE_BYTES)     // 230400

// idesc kind::f8f6f4: F32 accum (bit4), a/b=E4M3 (0), N=128, M=128
#define IDESC8 ((1u<<4) | ((128u/8u)<<17) | ((128u/16u)<<24))

__device__ __align__(1024) uint8_t g_x8[(size_t)NROWS * DIM];  // xn*32, e4m3
__device__ float g_partial2[2][CHUNKS][NROWS];   // [col-half][chunk][row]
__device__ float g_target[NROWS];    // 1024*sim(i, i^1)

// ---------------------------------------------------------------------------
// PTX helpers
// ---------------------------------------------------------------------------
__device__ __forceinline__ uint32_t smem_u32(const void* p) {
    uint32_t a;
    asm("{ .reg .u64 t; cvta.to.shared.u64 t, %1; cvt.u32.u64 %0, t; }"
        : "=r"(a) : "l"(p));
    return a;
}
__device__ __forceinline__ float fast_exp2(float a) {
    float r; asm("ex2.approx.f32 %0, %1;" : "=f"(r) : "f"(a)); return r;
}
__device__ __forceinline__ float fast_lg2(float a) {
    float r; asm("lg2.approx.f32 %0, %1;" : "=f"(r) : "f"(a)); return r;
}
__device__ __forceinline__ uint32_t cluster_rank() {
    uint32_t r; asm("mov.u32 %0, %%cluster_ctarank;" : "=r"(r)); return r;
}
__device__ __forceinline__ uint16_t cvt_e4m3x2(float hi, float lo) {
    uint16_t p;
    asm("cvt.rn.satfinite.e4m3x2.f32 %0, %1, %2;" : "=h"(p) : "f"(hi), "f"(lo));
    return p;
}
#define CLUSTER_SYNC() do { \
    asm volatile("barrier.cluster.arrive.aligned;" ::: "memory"); \
    asm volatile("barrier.cluster.wait.aligned;" ::: "memory"); } while (0)

#define MBARRIER_INIT(a, n) \
    asm volatile("mbarrier.init.shared.b64 [%0], %1;" :: "r"((uint32_t)(a)), "r"((uint32_t)(n)) : "memory")
#define MBARRIER_ARRIVE(a) \
    asm volatile("mbarrier.arrive.shared.b64 _, [%0];" :: "r"((uint32_t)(a)) : "memory")
#define MBARRIER_EXPECT_TX(a, tx) \
    asm volatile("mbarrier.arrive.expect_tx.shared.b64 _, [%0], %1;" \
        :: "r"((uint32_t)(a)), "r"((uint32_t)(tx)) : "memory")
#define MBARRIER_WAIT_PARITY(a, par) do { \
    uint32_t _m = (uint32_t)(a); uint32_t _p = (uint32_t)(par); uint32_t _d; \
    asm volatile("{\n\t.reg .pred p;\n\t" \
        "mbarrier.try_wait.parity.acquire.cta.shared::cta.b64 p, [%1], %2;\n\t" \
        "selp.b32 %0, 1, 0, p;\n\t}" : "=r"(_d) : "r"(_m), "r"(_p) : "memory"); \
    if (!_d) { \
        asm volatile("{\n\t.reg .pred P1;\n\t" \
            "WL_%=:\n\t" \
            "mbarrier.try_wait.parity.acquire.cta.shared::cta.b64 P1, [%0], %1, 0x989680;\n\t" \
            "@P1 bra.uni WD_%=;\n\t" \
            "bra.uni WL_%=;\n\t" \
            "WD_%=:\n\t}" :: "r"(_m), "r"(_p) : "memory"); \
    } } while (0)

#define TCGEN05_ALLOC(sa, n) \
    asm volatile("tcgen05.alloc.cta_group::1.sync.aligned.shared::cta.b32 [%0], %1;" \
        :: "r"((uint32_t)(sa)), "r"((uint32_t)(n)) : "memory")
#define TCGEN05_DEALLOC(t, n) \
    asm volatile("tcgen05.dealloc.cta_group::1.sync.aligned.b32 %0, %1;" :: "r"(t), "r"((uint32_t)(n)))
#define TCGEN05_RELINQ() \
    asm volatile("tcgen05.relinquish_alloc_permit.cta_group::1.sync.aligned;")
#define TCGEN05_COMMIT(a) \
    asm volatile("tcgen05.commit.cta_group::1.mbarrier::arrive::one.shared::cluster.b64 [%0];" \
        :: "r"((uint32_t)(a)) : "memory")
#define TCGEN05_COMMIT_MCAST(a, mask) \
    asm volatile("tcgen05.commit.cta_group::1.mbarrier::arrive::one.shared::cluster.multicast::cluster.b64 [%0], %1;" \
        :: "r"((uint32_t)(a)), "h"((uint16_t)(mask)) : "memory")
#define TCGEN05_FENCE_BEFORE() asm volatile("tcgen05.fence::before_thread_sync;" ::: "memory")
#define TCGEN05_FENCE_AFTER()  asm volatile("tcgen05.fence::after_thread_sync;" ::: "memory")
#define TCGEN05_WAIT_LD()      asm volatile("tcgen05.wait::ld.sync.aligned;" ::: "memory")

// plain 2D TMA (shared::cta) and multicast variant
#define TMA_2D(dst, tmapp, cx, cy, mbar) \
    asm volatile("cp.async.bulk.tensor.2d.shared::cta.global.tile" \
        ".mbarrier::complete_tx::bytes [%0], [%1, {%2, %3}], [%4];" \
        :: "r"((uint32_t)(dst)), "l"(tmapp), "r"((int)(cx)), "r"((int)(cy)), \
           "r"((uint32_t)(mbar)) : "memory")
#define TMA_2D_MCAST(dst, tmapp, cx, cy, mbar, mask) \
    asm volatile("cp.async.bulk.tensor.2d.shared::cluster.global.tile" \
        ".mbarrier::complete_tx::bytes.multicast::cluster [%0], [%1, {%2, %3}], [%4], %5;" \
        :: "r"((uint32_t)(dst)), "l"(tmapp), "r"((int)(cx)), "r"((int)(cy)), \
           "r"((uint32_t)(mbar)), "h"((uint16_t)(mask)) : "memory")

#define TCGEN05_LD_32X32B_X32(r, tmem_addr) \
    asm volatile( \
        "tcgen05.ld.sync.aligned.32x32b.x32.b32 " \
        "{%0, %1, %2, %3, %4, %5, %6, %7, " \
        " %8, %9, %10, %11, %12, %13, %14, %15, " \
        " %16, %17, %18, %19, %20, %21, %22, %23, " \
        " %24, %25, %26, %27, %28, %29, %30, %31}, [%32];" \
        : "=r"((r)[0]),  "=r"((r)[1]),  "=r"((r)[2]),  "=r"((r)[3]), \
          "=r"((r)[4]),  "=r"((r)[5]),  "=r"((r)[6]),  "=r"((r)[7]), \
          "=r"((r)[8]),  "=r"((r)[9]),  "=r"((r)[10]), "=r"((r)[11]), \
          "=r"((r)[12]), "=r"((r)[13]), "=r"((r)[14]), "=r"((r)[15]), \
          "=r"((r)[16]), "=r"((r)[17]), "=r"((r)[18]), "=r"((r)[19]), \
          "=r"((r)[20]), "=r"((r)[21]), "=r"((r)[22]), "=r"((r)[23]), \
          "=r"((r)[24]), "=r"((r)[25]), "=r"((r)[26]), "=r"((r)[27]), \
          "=r"((r)[28]), "=r"((r)[29]), "=r"((r)[30]), "=r"((r)[31]) \
        : "r"(tmem_addr))

// SW128 SMEM descriptor (layout=2, version=1, LBO=1, SBO=64); +2 per K=32 fp8.
__device__ __forceinline__ uint64_t make_desc(uint32_t addr) {
    return ((uint64_t)2 << 61) | ((uint64_t)1 << 46) | ((uint64_t)64 << 32) |
           ((uint64_t)1 << 16) | (uint64_t)((addr >> 4) & 0x3FFF);
}

#if defined(__CUDA_ARCH__) && defined(__CUDA_ARCH_FEAT_SM103_ALL)
#define HAS_TCGEN05 1
// SS form, fp8: A and B both via SMEM descriptors
__device__ __forceinline__ void mma_f8_ss(uint32_t d, uint64_t ad, uint64_t bd,
                                          uint32_t idesc, uint32_t en) {
    asm volatile(
        "{\n\t"
        ".reg .pred p;\n\t"
        "setp.ne.u32 p, %4, 0;\n\t"
        "tcgen05.mma.cta_group::1.kind::f8f6f4 [%0], %1, %2, %3, {%5, %5, %5, %5}, p;\n\t"
        "}"
        :: "r"(d), "l"(ad), "l"(bd), "r"(idesc), "r"(en), "r"(0u)
        : "memory");
}
#endif

// ---------------------------------------------------------------------------
// Kernel 1: warp-per-row normalize fp32 -> e4m3 (scaled by 32)
// ---------------------------------------------------------------------------
__global__ __launch_bounds__(256) void knorm(const float* __restrict__ x) {
    int row = (blockIdx.x << 3) + (threadIdx.x >> 5);
    int l   = threadIdx.x & 31;
    const float4* xr = (const float4*)(x + (size_t)row * DIM) + l * 6;

    float4 v[6];
    float ss = 0.f;
    #pragma unroll
    for (int u = 0; u < 6; u++) {
        v[u] = xr[u];
        ss = fmaf(v[u].x, v[u].x, ss);
        ss = fmaf(v[u].y, v[u].y, ss);
        ss = fmaf(v[u].z, v[u].z, ss);
        ss = fmaf(v[u].w, v[u].w, ss);
    }
    #pragma unroll
    for (int o = 16; o; o >>= 1) ss += __shfl_xor_sync(0xffffffffu, ss, o);
    float scale = 32.0f / fmaxf(sqrtf(ss), 1e-8f);

    uint32_t o[6];
    #pragma unroll
    for (int u = 0; u < 6; u++) {
        uint32_t lo = cvt_e4m3x2(v[u].y * scale, v[u].x * scale);
        uint32_t hi = cvt_e4m3x2(v[u].w * scale, v[u].z * scale);
        o[u] = lo | (hi << 16);
    }
    uint32_t* dst = (uint32_t*)(g_x8 + (size_t)row * DIM) + l * 6;
    *(uint2*)&dst[0] = make_uint2(o[0], o[1]);
    *(uint2*)&dst[2] = make_uint2(o[2], o[3]);
    *(uint2*)&dst[4] = make_uint2(o[4], o[5]);
}

// ---------------------------------------------------------------------------
// Kernel 2: logits' = (32 xn)(32 xn)^T = 1024*sim, fused exp-sum epilogue.
// SS-mode fp8 tcgen05, A persistent in SMEM (async TMA), B 8-stage TMA-mcast
// pipeline (cluster of 2), 4 D buffers of N=128 in TMEM.
// 8 consumer warps: warp w and w+4 share a TMEM subpartition and split each
// tile's 128 columns (64 each) -> LDTM wait of one hides under EX2 of the
// other. Warp 8 lane 0 = MMA issuer; warp 9 lane 0 = TMA producer.
// ---------------------------------------------------------------------------
__global__ __launch_bounds__(NTHREADS, 1) __cluster_dims__(2, 1, 1)
void kgemm(const __grid_constant__ CUtensorMap tmap) {
    extern __shared__ char smem[];
    const int tid   = threadIdx.x;
    const int i0    = blockIdx.x * 128;
    const int jbase = blockIdx.y * COLS_PER_CTA;

#if defined(HAS_TCGEN05)
    const uint32_t sb  = smem_u32(smem);
    const int wid = tid >> 5;

    const uint32_t MB_BFULL = sb + 16;     // 8 (count 1 + tx)
    const uint32_t MB_BFREE = sb + 80;     // 8 (count 2: both issuers)
    const uint32_t MB_MDONE = sb + 144;    // 4 (count 1)
    const uint32_t MB_DFREE = sb + 176;    // 4 (count 256)
    const uint32_t MB_ABAR  = sb + 208;    // 1 (count 1 + tx 96KB)

    if (tid == 0) {
        #pragma unroll
        for (int s = 0; s < NSTAGE; s++) {
            MBARRIER_INIT(MB_BFULL + s * 8, 1);
            MBARRIER_INIT(MB_BFREE + s * 8, 2);
        }
        #pragma unroll
        for (int b = 0; b < NDBUF; b++) {
            MBARRIER_INIT(MB_MDONE + b * 8, 1);
            MBARRIER_INIT(MB_DFREE + b * 8, 256);
        }
        MBARRIER_INIT(MB_ABAR, 1);
    }
    if (wid == 8) TCGEN05_ALLOC(sb, 512);
    __syncthreads();
    uint32_t tmem;
    asm volatile("ld.shared.b32 %0, [%1];" : "=r"(tmem) : "r"(sb));
    // Both CTAs' mbarriers must be visible before any multicast TMA/commit.
    CLUSTER_SYNC();

    if (wid < 8) {
        // ====== consumers: warps w / w+4 split each tile's columns ==========
        const int l  = tid & 31;
        const int sp = wid & 3;             // TMEM subpartition (row group)
        const int ch = wid >> 2;            // column half 0/1
        const int i  = i0 + sp * 32 + l;
        const uint32_t dcol = (uint32_t)(ch * 64);
        float partial = 0.f;
        #pragma unroll 1
        for (int t = 0; t < NTILE; t++) {
            const int b = t & (NDBUF - 1);
            MBARRIER_WAIT_PARITY(MB_MDONE + b * 8, (t >> 2) & 1);
            TCGEN05_FENCE_AFTER();
            const int j0 = jbase + t * 128 + ch * 64;
            uint32_t r0[32], r1[32];
            TCGEN05_LD_32X32B_X32(r0, tmem + b * 128 + dcol);
            TCGEN05_LD_32X32B_X32(r1, tmem + b * 128 + dcol + 32);
            TCGEN05_WAIT_LD();
            #pragma unroll
            for (int g = 0; g < 2; g++) {
                const uint32_t* rr = g ? r1 : r0;
                const int jg = j0 + g * 32;
                unsigned di = (unsigned)(i - jg);
                unsigned dt = (unsigned)((i ^ 1) - jg);
                if (di < 32u || dt < 32u) {
                    #pragma unroll
                    for (int c = 0; c < 32; c++) {
                        float v = __uint_as_float(rr[c]);
                        int j = jg + c;
                        if (j == (i ^ 1)) g_target[i] = v;
                        if (j != i)
                            partial += fast_exp2(fmaf(v, EXPC2, -EXPC));
                    }
                } else {
                    #pragma unroll
                    for (int c = 0; c < 32; c++)
                        partial += fast_exp2(fmaf(__uint_as_float(rr[c]), EXPC2, -EXPC));
                }
            }
            TCGEN05_FENCE_BEFORE();
            MBARRIER_ARRIVE(MB_DFREE + b * 8);
        }
        g_partial2[ch][blockIdx.y][i] = partial;
    } else if (tid == 256) {
        // ================= MMA issuer (fp8 SS) =================
        MBARRIER_WAIT_PARITY(MB_ABAR, 0);        // A resident in SMEM
        #pragma unroll 1
        for (int t = 0; t < NTILE; t++) {
            const int b = t & (NDBUF - 1);
            const uint32_t dD = tmem + b * 128;
            if (t >= NDBUF) {
                MBARRIER_WAIT_PARITY(MB_DFREE + b * 8, ((t >> 2) + 1) & 1);
                TCGEN05_FENCE_AFTER();
            }
            #pragma unroll 1
            for (int c = 0; c < KCPT; c++) {
                const int n = t * KCPT + c, s = n & (NSTAGE - 1), k = n >> 3;
                MBARRIER_WAIT_PARITY(MB_BFULL + s * 8, k & 1);
                uint64_t ad = make_desc(sb + A_OFF + c * 16384);
                uint64_t bd = make_desc(sb + B_OFF + s * STAGE_BYTES);
                #pragma unroll
                for (int k4 = 0; k4 < 4; k4++)       // K=32 per dispatch
                    mma_f8_ss(dD, ad + k4 * 2, bd + k4 * 2, IDESC8,
                              (uint32_t)((c | k4) != 0));
                // free stage s in BOTH CTAs only when each CTA's mmas are done
                TCGEN05_COMMIT_MCAST(MB_BFREE + s * 8, 0x3);
            }
            TCGEN05_COMMIT(MB_MDONE + b * 8);
        }
    } else if (tid == 288) {
        // ============ producer: A (async, plain TMA) then B (multicast) =====
        const int rank = (int)cluster_rank();        // 0/1 within pair
        MBARRIER_EXPECT_TX(MB_ABAR, 6 * 16384);
        #pragma unroll
        for (int c = 0; c < KCPT; c++) {
            TMA_2D(sb + A_OFF + c * 16384,        &tmap, c * 128, i0,      MB_ABAR);
            TMA_2D(sb + A_OFF + c * 16384 + 8192, &tmap, c * 128, i0 + 64, MB_ABAR);
        }
        #pragma unroll 1
        for (int n = 0; n < NCHUNK; n++) {
            const int s = n & (NSTAGE - 1), k = n >> 3;
            if (k >= 1) MBARRIER_WAIT_PARITY(MB_BFREE + s * 8, (k - 1) & 1);
            MBARRIER_EXPECT_TX(MB_BFULL + s * 8, STAGE_BYTES);
            const int t = n / KCPT, c = n % KCPT;
            const int y = jbase + t * 128 + rank * 64;     // this CTA's 64 rows
            const uint32_t stg = sb + B_OFF + s * STAGE_BYTES + rank * 8192;
            TMA_2D_MCAST(stg, &tmap, c * 128, y, MB_BFULL + s * 8, 0x3);
        }
    }
    // remaining lanes of warps 8/9 fall through

    __syncthreads();
    if (wid == 8) {
        TCGEN05_RELINQ();
        TCGEN05_DEALLOC(tmem, 512);
    }
    CLUSTER_SYNC();   // no CTA exits while peer multicast may be in flight
#else
    // ============ scalar fallback (non-103a compile passes; never runs) =====
    if (tid < 128) {
        const int i = i0 + tid;
        const uint8_t* xi = g_x8 + (size_t)i * DIM;
        float p0 = 0.f, p1 = 0.f;
        for (int j = jbase; j < jbase + COLS_PER_CTA; j++) {
            const uint8_t* xj = g_x8 + (size_t)j * DIM;
            float v = 0.f;
            for (int k = 0; k < DIM; k++) {
                float a = float(*reinterpret_cast<const __nv_fp8_e4m3*>(&xi[k]));
                float bq = float(*reinterpret_cast<const __nv_fp8_e4m3*>(&xj[k]));
                v = fmaf(a, bq, v);
            }
            if (j == (i ^ 1)) g_target[i] = v;
            if (j != i) {
                if ((j >> 6) & 1) p1 += fast_exp2(fmaf(v, EXPC2, -EXPC));
                else              p0 += fast_exp2(fmaf(v, EXPC2, -EXPC));
            }
        }
        g_partial2[0][blockIdx.y][i] = p0;
        g_partial2[1][blockIdx.y][i] = p1;
    }
#endif
}

// ---------------------------------------------------------------------------
// Kernel 3: loss_i = 20 + ln(S_i) - (20/1024)*v_target_i ; out = mean(loss)
// ---------------------------------------------------------------------------
__global__ __launch_bounds__(1024) void kreduce(float* __restrict__ out) {
    int tid = threadIdx.x;
    float s = 0.f;
    for (int i = tid; i < NROWS; i += 1024) {
        float S = (g_partial2[0][0][i] + g_partial2[0][1][i]) +
                  (g_partial2[1][0][i] + g_partial2[1][1][i]);
        s += 20.0f + LN2 * fast_lg2(S) - TSCALE * g_target[i];
    }
    #pragma unroll
    for (int o = 16; o; o >>= 1) s += __shfl_xor_sync(0xffffffffu, s, o);

    __shared__ float sw[32];
    if ((tid & 31) == 0) sw[tid >> 5] = s;
    __syncthreads();
    if (tid < 32) {
        s = sw[tid];
        #pragma unroll
        for (int o = 16; o; o >>= 1) s += __shfl_xor_sync(0xffffffffu, s, o);
        if (tid == 0) out[0] = s * (1.0f / NROWS);
    }
}

// ---------------------------------------------------------------------------
typedef CUresult (*PFN_encodeTiled)(
    CUtensorMap*, CUtensorMapDataType, cuuint32_t, void*,
    const cuuint64_t*, const cuuint64_t*, const cuuint32_t*, const cuuint32_t*,
    CUtensorMapInterleave, CUtensorMapSwizzle, CUtensorMapL2promotion,
    CUtensorMapFloatOOBfill);

extern "C" void kernel_launch(void* const* d_in, const int* in_sizes, int n_in,
                              void* d_out, int out_size) {
    const float* x = (const float*)d_in[0];
    float* out = (float*)d_out;

    // Tensormap for g_x8 as [NROWS, DIM] uint8, box [128, 64], SW128.
    // Host-CPU only (no enqueue) -> safe under graph capture; deterministic.
    static CUtensorMap tmap;
    void* fn = nullptr;
    cudaDriverEntryPointQueryResult qres;
    cudaGetDriverEntryPointByVersion("cuTensorMapEncodeTiled", &fn, 12000,
                                     cudaEnableDefault, &qres);
    void* xaddr = nullptr;
    cudaGetSymbolAddress(&xaddr, g_x8);
    if (fn && xaddr) {
        cuuint64_t dims[2]    = {(cuuint64_t)DIM, (cuuint64_t)NROWS};
        cuuint64_t strides[1] = {(cuuint64_t)DIM};
        cuuint32_t box[2]     = {128, 64};
        cuuint32_t estr[2]    = {1, 1};
        ((PFN_encodeTiled)fn)(&tmap, CU_TENSOR_MAP_DATA_TYPE_UINT8, 2, xaddr,
                              dims, strides, box, estr,
                              CU_TENSOR_MAP_INTERLEAVE_NONE,
                              CU_TENSOR_MAP_SWIZZLE_128B,
                              CU_TENSOR_MAP_L2_PROMOTION_L2_128B,
                              CU_TENSOR_MAP_FLOAT_OOB_FILL_NONE);
    }

    cudaFuncSetAttribute(kgemm, cudaFuncAttributeMaxDynamicSharedMemorySize, SMEM_TOTAL);

    knorm<<<NROWS / 8, 256>>>(x);
    kgemm<<<dim3(NROWS / 128, CHUNKS), NTHREADS, SMEM_TOTAL>>>(tmap);
    kreduce<<<1, 1024>>>(out);
}